// round 4
// baseline (speedup 1.0000x reference)
#include <cuda_runtime.h>

// Problem constants (fixed by the dataset: B=32, N=1024, D=32, k = N//5 = 204)
#define BB      32
#define NN      1024
#define DD      32
#define KSEL    204
#define THREADS 256
#define ROWS_PER_CTA 4        // 2 warps per row

// Output layout (float32 concat of x, edge_index, edge_attr_emb)
#define X_ELEMS   (BB * NN * DD)            // 1,048,576
#define E_EDGES   ((long)BB * NN * KSEL)    // 6,684,672
#define EI_OFF    ((long)X_ELEMS)
#define EA_OFF    (EI_OFF + 2 * E_EDGES)    // 14,417,920

// Shared layout (bytes): slocs 8KB | 4 x 2KB row scratch | W 128 | b 128 | cnt 16
#define SMEM_BYTES (8192 + 8192 + 256 + 32)

#define ROW_BAR() asm volatile("bar.sync %0, 64;" :: "r"(rw + 1) : "memory")

__device__ __forceinline__ void ce_reg(unsigned long long& a, unsigned long long& b, bool up)
{
    bool sw = up ? (a > b) : (a < b);
    unsigned long long t = a;
    a = sw ? b : a;
    b = sw ? t : b;
}

__global__ __launch_bounds__(THREADS, 6)
void edge_knn_kernel(const float2* __restrict__ locs,
                     const float*  __restrict__ emb,
                     const float*  __restrict__ Wv,
                     const float*  __restrict__ bv,
                     float*        __restrict__ out)
{
    extern __shared__ unsigned char smem[];
    float2*        slocs   = (float2*)smem;                         // [1024]
    unsigned char* scratch = smem + 8192;                           // 4 x 2KB
    float*         sW      = (float*)(smem + 8192 + 8192);          // [32]
    float*         sB      = sW + 32;                               // [32]
    unsigned*      scnt    = (unsigned*)(smem + 8192 + 8192 + 256); // [4]

    const int tid  = threadIdx.x;
    const int lane = tid & 31;
    const int w    = tid >> 5;
    const int rw   = w >> 1;              // row within CTA, 0..3
    const int half = w & 1;               // which half of the row's 64 lanes
    const int l6   = half * 32 + lane;    // 0..63
    const int cta  = blockIdx.x;          // 8192 CTAs
    const int batch = cta >> 8;           // 256 CTAs per batch instance
    const int i0    = (cta & 255) << 2;   // 4 rows per CTA

    // ---- x copy: 8192 CTAs x 32 float4 == X_ELEMS ----
    if (tid < 32)
        __stcs(((float4*)out) + cta * 32 + tid, ((const float4*)emb)[cta * 32 + tid]);

    // ---- stage batch locs + W/b into shared ----
    #pragma unroll
    for (int t = tid; t < NN; t += THREADS)
        slocs[t] = locs[batch * NN + t];
    if (tid < 32)      sW[tid]      = Wv[tid];
    else if (tid < 64) sB[tid - 32] = bv[tid - 32];
    __syncthreads();

    // ================= per-row (2 warps cooperate) =================
    const int i = i0 + rw;
    const float2 mi = slocs[i];
    unsigned long long* cand = (unsigned long long*)(scratch + rw * 2048); // [256]
    unsigned* hist = (unsigned*)cand;     // alias (1KB) inside scratch
    float*    sd   = (float*)cand;        // alias: stride-5 dist floats

    // zero hist (256 bins across 64 lanes)
    #pragma unroll
    for (int r = 0; r < 4; ++r) hist[l6 + 64 * r] = 0u;
    if (l6 == 0) scnt[rw] = 0u;
    ROW_BAR();

    // ---- pass 1: squared distances -> 256-bin histogram (uniform in sq) ----
    // sq = dx*dx + dy*dy with NO fma contraction (bit-exact vs reference).
    #pragma unroll 4
    for (int it = 0; it < 16; ++it) {
        int j = half * 512 + it * 32 + lane;
        float2 lj = slocs[j];
        float dx = mi.x - lj.x;
        float dy = mi.y - lj.y;
        float sq = __fadd_rn(__fmul_rn(dx, dx), __fmul_rn(dy, dy));
        if (j != i) {
            int bin = (int)(__fmul_rn(sq, 128.0f));   // sq in [0,2) -> [0,256)
            bin = bin > 255 ? 255 : bin;
            atomicAdd(&hist[bin], 1u);
        }
    }
    ROW_BAR();

    // ---- threshold bin (each warp computes the identical result) ----
    unsigned h[8];
    int lsum = 0;
    #pragma unroll
    for (int r = 0; r < 8; ++r) { h[r] = hist[lane * 8 + r]; lsum += (int)h[r]; }
    int incl = lsum;
    #pragma unroll
    for (int o = 1; o < 32; o <<= 1) {
        int v = __shfl_up_sync(0xFFFFFFFFu, incl, o);
        if (lane >= o) incl += v;
    }
    int c  = incl - lsum;
    int tb = 256;
    #pragma unroll
    for (int r = 0; r < 8; ++r) {
        c += (int)h[r];
        if (c >= KSEL && tb == 256) tb = lane * 8 + r;
    }
    #pragma unroll
    for (int o = 16; o; o >>= 1) {
        int v = __shfl_xor_sync(0xFFFFFFFFu, tb, o);
        tb = v < tb ? v : tb;
    }
    ROW_BAR();   // hist reads complete; cand region may be overwritten
    const float thr = (float)(tb + 1);   // trunc(sq*128) <= tb  <=>  sq*128 < tb+1

    // ---- pass 2: recompute sq, compact (sq*128 < thr) via shared counter ----
    #pragma unroll 4
    for (int it = 0; it < 16; ++it) {
        int j = half * 512 + it * 32 + lane;
        float2 lj = slocs[j];
        float dx = mi.x - lj.x;
        float dy = mi.y - lj.y;
        float sq = __fadd_rn(__fmul_rn(dx, dx), __fmul_rn(dy, dy));
        bool take = (j != i) && (__fmul_rn(sq, 128.0f) < thr);
        unsigned m = __ballot_sync(0xFFFFFFFFu, take);
        int base = 0;
        if (lane == 0) base = (int)atomicAdd(&scnt[rw], (unsigned)__popc(m));
        base = __shfl_sync(0xFFFFFFFFu, base, 0);
        int pos = base + __popc(m & ((1u << lane) - 1u));
        if (take && pos < 256)
            cand[pos] = ((unsigned long long)__float_as_uint(sq) << 32) | (unsigned)j;
    }
    ROW_BAR();

    // ---- pad to 256 with +inf keys ----
    int total = (int)scnt[rw];
    total = total > 256 ? 256 : total;
    for (int p = total + l6; p < 256; p += 64)
        cand[p] = ((unsigned long long)0x7F800000u << 32) | 0xFFFFFFFFu;
    ROW_BAR();

    // ---- load 4 keys/lane, sqrt only on 256 survivors ----
    // network element e = l6*4 + r: bits0-1=r, bits2-6=lane, bit7=half
    unsigned long long key[4];
    #pragma unroll
    for (int r = 0; r < 4; ++r) {
        unsigned long long v = cand[l6 * 4 + r];
        float d = __fsqrt_rn(__uint_as_float((unsigned)(v >> 32)));  // sqrt(inf)=inf
        key[r] = ((unsigned long long)__float_as_uint(d) << 32) | (unsigned)v;
    }

    // ---- bitonic sort of 256 u64 keys across 64 lanes ----
    // kl = 1: stride 1, direction from e bit1 (= r bit1)
    ce_reg(key[0], key[1], true);
    ce_reg(key[2], key[3], false);

    #pragma unroll
    for (int kl = 2; kl <= 8; ++kl) {
        const bool up = (kl <= 6) ? (((lane >> (kl - 2)) & 1) == 0)
                       : (kl == 7) ? (half == 0) : true;
        #pragma unroll
        for (int sl = kl - 1; sl >= 0; --sl) {
            if (sl == 7) {
                // single cross-warp stage (kl==8, up==true): exchange via smem
                #pragma unroll
                for (int r = 0; r < 4; ++r) cand[l6 * 4 + r] = key[r];
                ROW_BAR();
                #pragma unroll
                for (int r = 0; r < 4; ++r) {
                    unsigned long long other = cand[(l6 * 4 + r) ^ 128];
                    bool less = key[r] < other;
                    bool keepMin = (half == 0);
                    key[r] = (less == keepMin) ? key[r] : other;
                }
            } else if (sl >= 2) {
                const int ls = 1 << (sl - 2);          // lane stride
                const bool keepMin = ((((lane >> (sl - 2)) & 1) == 0) == up);
                #pragma unroll
                for (int r = 0; r < 4; ++r) {
                    unsigned long long other = __shfl_xor_sync(0xFFFFFFFFu, key[r], ls);
                    bool less = key[r] < other;
                    key[r] = (less == keepMin) ? key[r] : other;
                }
            } else if (sl == 1) {
                ce_reg(key[0], key[2], up);
                ce_reg(key[1], key[3], up);
            } else {
                ce_reg(key[0], key[1], up);
                ce_reg(key[2], key[3], up);
            }
        }
    }
    ROW_BAR();   // partner reads of cand (cross-warp stage) are done; safe to reuse
    // lane l6 now holds sorted ranks l6*4 .. l6*4+3

    // ---- emission ----
    const long  row  = (long)batch * NN + i;
    float* o_src = out + EI_OFF;
    float* o_dst = o_src + E_EDGES;
    float* o_ea  = out + EA_OFF;
    const float srcv = (float)row;
    const int   jbase = batch * NN;

    // edge_index from registers: 51 lanes x 4 ranks == KSEL exactly
    if (l6 < 51) {
        float* ps = o_src + row * KSEL + l6 * 4;
        float* pd = o_dst + row * KSEL + l6 * 4;
        __stcs((float4*)ps, make_float4(srcv, srcv, srcv, srcv));
        __stcs((float4*)pd, make_float4(
            (float)(jbase + (int)(unsigned)key[0]),
            (float)(jbase + (int)(unsigned)key[1]),
            (float)(jbase + (int)(unsigned)key[2]),
            (float)(jbase + (int)(unsigned)key[3])));
    }

    // dump dist floats to stride-5 smem (odd stride -> conflict-free)
    #pragma unroll
    for (int r = 0; r < 4; ++r)
        sd[l6 * 5 + r] = __uint_as_float((unsigned)(key[r] >> 32));
    ROW_BAR();

    // edge_attr_emb: out[e, c] = d * W[c] + b[c]; 8 edges x 32 dims per iter
    const int eg = l6 >> 3;            // which of 8 edges this lane covers
    const int c4 = (l6 & 7) * 4;       // 4 embedding dims
    const float4 W4 = *(const float4*)(sW + c4);
    const float4 B4 = *(const float4*)(sB + c4);
    float* eabase = o_ea + row * (long)(KSEL * DD);
    #pragma unroll 2
    for (int kk0 = 0; kk0 < KSEL; kk0 += 8) {
        int kk = kk0 + eg;             // last iter: only eg < 4 valid
        if (kk < KSEL) {
            float d = sd[(kk >> 2) * 5 + (kk & 3)];
            float4 o;
            o.x = fmaf(d, W4.x, B4.x);
            o.y = fmaf(d, W4.y, B4.y);
            o.z = fmaf(d, W4.z, B4.z);
            o.w = fmaf(d, W4.w, B4.w);
            __stcs((float4*)(eabase + (long)kk * DD + c4), o);
        }
    }
}

extern "C" void kernel_launch(void* const* d_in, const int* in_sizes, int n_in,
                              void* d_out, int out_size)
{
    const float2* locs = (const float2*)d_in[0];
    const float*  emb  = (const float*)d_in[1];
    const float*  Wv   = (const float*)d_in[2];
    const float*  bv   = (const float*)d_in[3];
    float* out = (float*)d_out;

    cudaFuncSetAttribute(edge_knn_kernel,
                         cudaFuncAttributeMaxDynamicSharedMemorySize, SMEM_BYTES);
    edge_knn_kernel<<<(BB * NN) / ROWS_PER_CTA, THREADS, SMEM_BYTES>>>(locs, emb, Wv, bv, out);
}

// round 5
// speedup vs baseline: 1.0753x; 1.0753x over previous
#include <cuda_runtime.h>

// Problem constants (fixed by the dataset: B=32, N=1024, D=32, k = N//5 = 204)
#define BB      32
#define NN      1024
#define DD      32
#define KSEL    204
#define THREADS 256
#define WARPS   8

// Output layout (float32 concat of x, edge_index, edge_attr_emb)
#define X_ELEMS   (BB * NN * DD)            // 1,048,576
#define E_EDGES   ((long)BB * NN * KSEL)    // 6,684,672
#define EI_OFF    ((long)X_ELEMS)
#define EA_OFF    (EI_OFF + 2 * E_EDGES)    // 14,417,920

// Shared layout (bytes): slocs 8KB | per-warp scratch 8*2KB | W/b 256B
#define SMEM_BYTES (8192 + 16384 + 256)

__global__ __launch_bounds__(THREADS, 5)
void edge_knn_kernel(const float2* __restrict__ locs,
                     const float*  __restrict__ emb,
                     const float*  __restrict__ Wv,
                     const float*  __restrict__ bv,
                     float*        __restrict__ out)
{
    extern __shared__ unsigned char smem[];
    float2*             slocs   = (float2*)smem;                       // [1024]
    unsigned char*      scratch = smem + 8192;                         // 8 x 2KB
    float*              sW      = (float*)(smem + 8192 + 16384);       // [32]
    float*              sB      = sW + 32;                             // [32]

    const int tid  = threadIdx.x;
    const int lane = tid & 31;
    const int w    = tid >> 5;
    const int cta  = blockIdx.x;          // 4096 CTAs
    const int batch = cta >> 7;           // 128 CTAs per batch instance
    const int i0    = (cta & 127) << 3;   // 8 rows per CTA (one per warp)

    // ---- x copy: out[0 : 1,048,576] = init_embeddings, 64 x st.128 per CTA ----
    if (tid < 64)
        __stcs(((float4*)out) + cta * 64 + tid, ((const float4*)emb)[cta * 64 + tid]);

    // ---- stage batch locs + W/b into shared ----
    #pragma unroll
    for (int t = tid; t < NN; t += THREADS)
        slocs[t] = locs[batch * NN + t];
    if (tid < 32)      sW[tid]      = Wv[tid];
    else if (tid < 64) sB[tid - 32] = bv[tid - 32];
    __syncthreads();

    // ================= per-warp: one row i =================
    const int i = i0 + w;
    const float2 mi = slocs[i];
    const float4* slocs4 = (const float4*)slocs;    // 512 point-pairs
    unsigned long long* mycand = (unsigned long long*)(scratch + w * 2048); // [256]
    unsigned* hist = (unsigned*)mycand;   // alias: hist (1KB) inside scratch
    float*    sd   = (float*)mycand;      // alias: padded dist floats

    // zero hist (as u64)
    #pragma unroll
    for (int r = 0; r < 4; ++r) ((unsigned long long*)hist)[lane + 32 * r] = 0ULL;
    __syncwarp();

    // ---- pass 1: squared distances -> 256-bin histogram (uniform in sq) ----
    // sq = dx*dx + dy*dy with NO fma contraction (bit-exact vs reference).
    #pragma unroll
    for (int it = 0; it < 16; ++it) {
        int idx = it * 32 + lane;          // pair index; points 2*idx, 2*idx+1
        float4 p = slocs4[idx];
        int j0 = idx * 2;
        float dx0 = mi.x - p.x, dy0 = mi.y - p.y;
        float sq0 = __fadd_rn(__fmul_rn(dx0, dx0), __fmul_rn(dy0, dy0));
        float dx1 = mi.x - p.z, dy1 = mi.y - p.w;
        float sq1 = __fadd_rn(__fmul_rn(dx1, dx1), __fmul_rn(dy1, dy1));
        if (j0 != i) {
            int b0 = (int)(__fmul_rn(sq0, 128.0f));
            b0 = b0 > 255 ? 255 : b0;
            atomicAdd(&hist[b0], 1u);
        }
        if (j0 + 1 != i) {
            int b1 = (int)(__fmul_rn(sq1, 128.0f));
            b1 = b1 > 255 ? 255 : b1;
            atomicAdd(&hist[b1], 1u);
        }
    }
    __syncwarp();

    // ---- threshold bin: first bin with cumulative count >= KSEL ----
    unsigned h[8];
    int lsum = 0;
    #pragma unroll
    for (int r = 0; r < 8; ++r) { h[r] = hist[lane * 8 + r]; lsum += (int)h[r]; }
    int incl = lsum;
    #pragma unroll
    for (int o = 1; o < 32; o <<= 1) {
        int v = __shfl_up_sync(0xFFFFFFFFu, incl, o);
        if (lane >= o) incl += v;
    }
    int c  = incl - lsum;   // exclusive prefix of this lane's 8 bins
    int tb = 256;
    #pragma unroll
    for (int r = 0; r < 8; ++r) {
        c += (int)h[r];
        if (c >= KSEL && tb == 256) tb = lane * 8 + r;
    }
    #pragma unroll
    for (int o = 16; o; o >>= 1) {
        int v = __shfl_xor_sync(0xFFFFFFFFu, tb, o);
        tb = v < tb ? v : tb;
    }
    __syncwarp();   // hist reads done; scratch may now be overwritten
    // trunc(sq*128) <= tb  <=>  sq*128 < tb+1  (exact for tb+1 <= 256)
    const float thr = (float)(tb + 1);
    const unsigned lm = (1u << lane) - 1u;

    // ---- pass 2: recompute sq, compact candidates (sq*128 < thr) ----
    int cnt = 0;
    #pragma unroll
    for (int it = 0; it < 16; ++it) {
        int idx = it * 32 + lane;
        float4 p = slocs4[idx];
        int j0 = idx * 2;
        float dx0 = mi.x - p.x, dy0 = mi.y - p.y;
        float sq0 = __fadd_rn(__fmul_rn(dx0, dx0), __fmul_rn(dy0, dy0));
        float dx1 = mi.x - p.z, dy1 = mi.y - p.w;
        float sq1 = __fadd_rn(__fmul_rn(dx1, dx1), __fmul_rn(dy1, dy1));
        bool take0 = (j0 != i)     && (__fmul_rn(sq0, 128.0f) < thr);
        bool take1 = (j0 + 1 != i) && (__fmul_rn(sq1, 128.0f) < thr);
        unsigned m0 = __ballot_sync(0xFFFFFFFFu, take0);
        unsigned m1 = __ballot_sync(0xFFFFFFFFu, take1);
        int pos0  = cnt + __popc(m0 & lm);
        int base1 = cnt + __popc(m0);
        int pos1  = base1 + __popc(m1 & lm);
        if (take0 && pos0 < 256)
            mycand[pos0] = ((unsigned long long)__float_as_uint(sq0) << 32) | (unsigned)j0;
        if (take1 && pos1 < 256)
            mycand[pos1] = ((unsigned long long)__float_as_uint(sq1) << 32) | (unsigned)(j0 + 1);
        cnt = base1 + __popc(m1);
    }
    int total = cnt > 256 ? 256 : cnt;    // >= KSEL by construction
    for (int p = total + lane; p < 256; p += 32)
        mycand[p] = ((unsigned long long)0x7F800000u << 32) | 0xFFFFFFFFu;  // +inf pad
    __syncwarp();

    // ---- load candidates (conflict-free), convert sq -> d on 256 survivors ----
    // Network element coordinates e = lane*8 + r (bits 0-2 = r, bits 3-7 = lane)
    // so strides 1,2,4 are register-local and only strides >=8 need SHFL.
    unsigned long long key[8];
    #pragma unroll
    for (int r = 0; r < 8; ++r) {
        unsigned long long v = mycand[r * 32 + lane];
        float d = __fsqrt_rn(__uint_as_float((unsigned)(v >> 32)));  // sqrt(inf)=inf
        key[r] = ((unsigned long long)__float_as_uint(d) << 32) | (unsigned)v;
    }
    __syncwarp();

    // ---- bitonic sort of 256 u64 keys, e = lane*8 + r ----
    #pragma unroll
    for (int kl = 1; kl <= 8; ++kl) {
        #pragma unroll
        for (int sl = kl - 1; sl >= 0; --sl) {
            if (sl >= 3) {
                const int ls = 1 << (sl - 3);          // lane stride
                const bool lowSide = ((lane & ls) == 0);
                // kl >= 4 here, so direction is lane-based
                const bool up = (((lane >> (kl - 3)) & 1) == 0);
                const bool keepMin = (lowSide == up);
                #pragma unroll
                for (int r = 0; r < 8; ++r) {
                    unsigned long long other = __shfl_xor_sync(0xFFFFFFFFu, key[r], ls);
                    bool less = key[r] < other;
                    key[r] = (less == keepMin) ? key[r] : other;
                }
            } else {
                const int s = 1 << sl;                 // register stride
                #pragma unroll
                for (int r = 0; r < 8; ++r) {
                    if ((r & s) == 0) {
                        const int r2 = r | s;
                        bool up = (kl < 3) ? (((r >> kl) & 1) == 0)
                                           : (((lane >> (kl - 3)) & 1) == 0);
                        unsigned long long a = key[r], b2 = key[r2];
                        bool sw = up ? (a > b2) : (a < b2);
                        key[r]  = sw ? b2 : a;
                        key[r2] = sw ? a  : b2;
                    }
                }
            }
        }
    }
    // lane L now holds sorted ranks L*8 .. L*8+7 in key[0..7]

    // ---- emission ----
    const long  row  = (long)batch * NN + i;         // global node id
    float* o_src = out + EI_OFF;
    float* o_dst = o_src + E_EDGES;
    float* o_ea  = out + EA_OFF;
    const float srcv = (float)row;
    const int   jbase = batch * NN;

    // edge_index straight from registers: lane covers kk = lane*8 .. lane*8+7
    {
        float dstf[8];
        #pragma unroll
        for (int r = 0; r < 8; ++r)
            dstf[r] = (float)(jbase + (int)(unsigned)key[r]);
        float* ps = o_src + row * KSEL + lane * 8;
        float* pd = o_dst + row * KSEL + lane * 8;
        const float4 s4 = make_float4(srcv, srcv, srcv, srcv);
        if (lane < 25) {
            __stcs((float4*)ps,     s4);
            __stcs((float4*)ps + 1, s4);
            __stcs((float4*)pd,     make_float4(dstf[0], dstf[1], dstf[2], dstf[3]));
            __stcs((float4*)pd + 1, make_float4(dstf[4], dstf[5], dstf[6], dstf[7]));
        } else if (lane == 25) {   // kk 200..203 only (KSEL = 204)
            __stcs((float4*)ps, s4);
            __stcs((float4*)pd, make_float4(dstf[0], dstf[1], dstf[2], dstf[3]));
        }
    }

    // dump dist floats to padded smem (stride 9 -> conflict-free)
    #pragma unroll
    for (int r = 0; r < 8; ++r)
        sd[lane * 9 + r] = __uint_as_float((unsigned)(key[r] >> 32));
    __syncwarp();

    // edge_attr_emb: out[e, c] = d * W[c] + b[c], float4-vectorized, coalesced
    const int eg = lane >> 3;          // which of 4 edges this lane covers
    const int c4 = (lane & 7) * 4;     // 4 embedding dims
    const float4 W4 = *(const float4*)(sW + c4);
    const float4 B4 = *(const float4*)(sB + c4);
    float* eabase = o_ea + row * (long)(KSEL * DD);
    #pragma unroll 4
    for (int kk0 = 0; kk0 < KSEL; kk0 += 4) {
        int kk = kk0 + eg;             // kk <= 203 always (204 = 4*51)
        float d = sd[(kk >> 3) * 9 + (kk & 7)];
        float4 o;
        o.x = fmaf(d, W4.x, B4.x);
        o.y = fmaf(d, W4.y, B4.y);
        o.z = fmaf(d, W4.z, B4.z);
        o.w = fmaf(d, W4.w, B4.w);
        __stcs((float4*)(eabase + (long)kk * DD + c4), o);
    }
}

extern "C" void kernel_launch(void* const* d_in, const int* in_sizes, int n_in,
                              void* d_out, int out_size)
{
    const float2* locs = (const float2*)d_in[0];
    const float*  emb  = (const float*)d_in[1];
    const float*  Wv   = (const float*)d_in[2];
    const float*  bv   = (const float*)d_in[3];
    float* out = (float*)d_out;

    cudaFuncSetAttribute(edge_knn_kernel,
                         cudaFuncAttributeMaxDynamicSharedMemorySize, SMEM_BYTES);
    edge_knn_kernel<<<(BB * NN) / WARPS, THREADS, SMEM_BYTES>>>(locs, emb, Wv, bv, out);
}

// round 6
// speedup vs baseline: 1.2262x; 1.1404x over previous
#include <cuda_runtime.h>

// Problem constants (fixed by the dataset: B=32, N=1024, D=32, k = N//5 = 204)
#define BB      32
#define NN      1024
#define DD      32
#define KSEL    204
#define THREADS 256
#define WARPS   8

// Output layout (float32 concat of x, edge_index, edge_attr_emb)
#define X_ELEMS   (BB * NN * DD)            // 1,048,576
#define E_EDGES   ((long)BB * NN * KSEL)    // 6,684,672
#define EI_OFF    ((long)X_ELEMS)
#define EA_OFF    (EI_OFF + 2 * E_EDGES)    // 14,417,920

// Shared layout (bytes): slocs 8KB | per-warp scratch 8*2KB | W/b 256B
#define SMEM_BYTES (8192 + 16384 + 256)

// 64-bit key held as two float-typed registers so selects compile to FSEL
// (fma pipe) instead of SEL (alu pipe). Pure bit moves — no FP arithmetic.
struct K64 { float lo, hi; };

__device__ __forceinline__ unsigned long long k64_bits(K64 k) {
    return ((unsigned long long)__float_as_uint(k.hi) << 32) | __float_as_uint(k.lo);
}
__device__ __forceinline__ K64 k64_make(unsigned long long v) {
    K64 k;
    k.lo = __uint_as_float((unsigned)v);
    k.hi = __uint_as_float((unsigned)(v >> 32));
    return k;
}
// compare as u64 (ISETP pair, alu); select as float (FSEL, fma)
__device__ __forceinline__ bool k64_lt(K64 a, K64 b) {
    return k64_bits(a) < k64_bits(b);     // bitcasts are free; compare is int
}
__device__ __forceinline__ K64 k64_sel(bool take_b, K64 a, K64 b) {
    K64 r;
    r.lo = take_b ? b.lo : a.lo;
    r.hi = take_b ? b.hi : a.hi;
    return r;
}

__global__ __launch_bounds__(THREADS, 5)
void edge_knn_kernel(const float2* __restrict__ locs,
                     const float*  __restrict__ emb,
                     const float*  __restrict__ Wv,
                     const float*  __restrict__ bv,
                     float*        __restrict__ out)
{
    extern __shared__ unsigned char smem[];
    float2*             slocs   = (float2*)smem;                       // [1024]
    unsigned char*      scratch = smem + 8192;                         // 8 x 2KB
    float*              sW      = (float*)(smem + 8192 + 16384);       // [32]
    float*              sB      = sW + 32;                             // [32]

    const int tid  = threadIdx.x;
    const int lane = tid & 31;
    const int w    = tid >> 5;
    const int cta  = blockIdx.x;          // 4096 CTAs
    const int batch = cta >> 7;           // 128 CTAs per batch instance
    const int i0    = (cta & 127) << 3;   // 8 rows per CTA (one per warp)

    // ---- x copy: out[0 : 1,048,576] = init_embeddings ----
    out[cta * THREADS + tid] = emb[cta * THREADS + tid];

    // ---- stage batch locs + W/b into shared ----
    #pragma unroll
    for (int t = tid; t < NN; t += THREADS)
        slocs[t] = locs[batch * NN + t];
    if (tid < 32)      sW[tid]      = Wv[tid];
    else if (tid < 64) sB[tid - 32] = bv[tid - 32];
    __syncthreads();

    // ================= per-warp: one row i =================
    const int i = i0 + w;
    const float2 mi = slocs[i];
    unsigned long long* mycand = (unsigned long long*)(scratch + w * 2048); // [256]
    unsigned* hist = (unsigned*)mycand;   // alias: hist (1KB) inside scratch
    float*    sd   = (float*)mycand;      // alias: padded dist floats

    // zero hist
    #pragma unroll
    for (int r = 0; r < 8; ++r) hist[lane + 32 * r] = 0u;
    __syncwarp();

    // ---- pass 1: squared distances -> 256-bin histogram (uniform in sq) ----
    // sq = dx*dx + dy*dy with NO fma contraction (bit-exact vs reference).
    #pragma unroll 4
    for (int it = 0; it < NN / 32; ++it) {
        int j = it * 32 + lane;
        float2 lj = slocs[j];
        float dx = mi.x - lj.x;
        float dy = mi.y - lj.y;
        float sq = __fadd_rn(__fmul_rn(dx, dx), __fmul_rn(dy, dy));
        if (j != i) {
            int bin = (int)(__fmul_rn(sq, 128.0f));   // sq in [0,2) -> [0,256)
            bin = bin > 255 ? 255 : bin;
            atomicAdd(&hist[bin], 1u);
        }
    }
    __syncwarp();

    // ---- threshold bin: first bin with cumulative count >= KSEL ----
    unsigned h[8];
    int lsum = 0;
    #pragma unroll
    for (int r = 0; r < 8; ++r) { h[r] = hist[lane * 8 + r]; lsum += (int)h[r]; }
    int incl = lsum;
    #pragma unroll
    for (int o = 1; o < 32; o <<= 1) {
        int v = __shfl_up_sync(0xFFFFFFFFu, incl, o);
        if (lane >= o) incl += v;
    }
    int c  = incl - lsum;   // exclusive prefix of this lane's 8 bins
    int tb = 256;
    #pragma unroll
    for (int r = 0; r < 8; ++r) {
        c += (int)h[r];
        if (c >= KSEL && tb == 256) tb = lane * 8 + r;
    }
    #pragma unroll
    for (int o = 16; o; o >>= 1) {
        int v = __shfl_xor_sync(0xFFFFFFFFu, tb, o);
        tb = v < tb ? v : tb;
    }
    __syncwarp();   // hist reads done; scratch may now be overwritten
    // trunc(sq*128) <= tb  <=>  sq*128 < tb+1  (exact for tb+1 <= 256)
    const float thr = (float)(tb + 1);

    // ---- pass 2: recompute sq, compact candidates (sq*128 < thr) ----
    int cnt = 0;
    #pragma unroll 4
    for (int it = 0; it < NN / 32; ++it) {
        int j = it * 32 + lane;
        float2 lj = slocs[j];
        float dx = mi.x - lj.x;
        float dy = mi.y - lj.y;
        float sq = __fadd_rn(__fmul_rn(dx, dx), __fmul_rn(dy, dy));
        bool take = (j != i) && (__fmul_rn(sq, 128.0f) < thr);
        unsigned m = __ballot_sync(0xFFFFFFFFu, take);
        int pos = cnt + __popc(m & ((1u << lane) - 1u));
        if (take && pos < 256)
            mycand[pos] = ((unsigned long long)__float_as_uint(sq) << 32) | (unsigned)j;
        cnt += __popc(m);
    }
    int total = cnt > 256 ? 256 : cnt;    // >= KSEL by construction
    for (int p = total + lane; p < 256; p += 32)
        mycand[p] = ((unsigned long long)0x7F800000u << 32) | 0xFFFFFFFFu;  // +inf pad
    __syncwarp();

    // ---- load candidates (conflict-free), convert sq -> d on 256 survivors ----
    // Network element coordinates e = lane*8 + r (bits 0-2 = r, bits 3-7 = lane)
    // so strides 1,2,4 are register-local and only strides >=8 need SHFL.
    K64 key[8];
    #pragma unroll
    for (int r = 0; r < 8; ++r) {
        unsigned long long v = mycand[r * 32 + lane];
        float d = __fsqrt_rn(__uint_as_float((unsigned)(v >> 32)));  // sqrt(inf)=inf
        key[r] = k64_make(((unsigned long long)__float_as_uint(d) << 32) | (unsigned)v);
    }
    __syncwarp();

    // ---- bitonic sort of 256 u64 keys, e = lane*8 + r ----
    #pragma unroll
    for (int kl = 1; kl <= 8; ++kl) {
        #pragma unroll
        for (int sl = kl - 1; sl >= 0; --sl) {
            if (sl >= 3) {
                const int ls = 1 << (sl - 3);          // lane stride
                const bool lowSide = ((lane & ls) == 0);
                // kl >= 4 here, so direction is lane-based
                const bool up = (((lane >> (kl - 3)) & 1) == 0);
                const bool keepMin = (lowSide == up);
                #pragma unroll
                for (int r = 0; r < 8; ++r) {
                    K64 other;
                    other.lo = __shfl_xor_sync(0xFFFFFFFFu, key[r].lo, ls);
                    other.hi = __shfl_xor_sync(0xFFFFFFFFu, key[r].hi, ls);
                    bool less = k64_lt(key[r], other);
                    key[r] = k64_sel(less != keepMin, key[r], other);
                }
            } else {
                const int s = 1 << sl;                 // register stride
                #pragma unroll
                for (int r = 0; r < 8; ++r) {
                    if ((r & s) == 0) {
                        const int r2 = r | s;
                        bool up = (kl < 3) ? (((r >> kl) & 1) == 0)
                                           : (((lane >> (kl - 3)) & 1) == 0);
                        K64 a = key[r], b2 = key[r2];
                        bool sw = up ? !k64_lt(a, b2) && k64_lt(b2, a)
                                     : k64_lt(a, b2);
                        // up: swap if a > b2  <=>  b2 < a
                        sw = up ? k64_lt(b2, a) : k64_lt(a, b2);
                        key[r]  = k64_sel(sw, a, b2);
                        key[r2] = k64_sel(sw, b2, a);
                    }
                }
            }
        }
    }
    // lane L now holds sorted ranks L*8 .. L*8+7 in key[0..7]

    // ---- emission ----
    const long  row  = (long)batch * NN + i;         // global node id
    float* o_src = out + EI_OFF;
    float* o_dst = o_src + E_EDGES;
    float* o_ea  = out + EA_OFF;
    const float srcv = (float)row;
    const int   jbase = batch * NN;

    // edge_index straight from registers: lane covers kk = lane*8 .. lane*8+7
    {
        float dstf[8];
        #pragma unroll
        for (int r = 0; r < 8; ++r)
            dstf[r] = (float)(jbase + (int)__float_as_uint(key[r].lo));
        float* ps = o_src + row * KSEL + lane * 8;
        float* pd = o_dst + row * KSEL + lane * 8;
        const float4 s4 = make_float4(srcv, srcv, srcv, srcv);
        if (lane < 25) {
            __stcs((float4*)ps,     s4);
            __stcs((float4*)ps + 1, s4);
            __stcs((float4*)pd,     make_float4(dstf[0], dstf[1], dstf[2], dstf[3]));
            __stcs((float4*)pd + 1, make_float4(dstf[4], dstf[5], dstf[6], dstf[7]));
        } else if (lane == 25) {   // kk 200..203 only (KSEL = 204)
            __stcs((float4*)ps, s4);
            __stcs((float4*)pd, make_float4(dstf[0], dstf[1], dstf[2], dstf[3]));
        }
    }

    // dump dist floats to padded smem (stride 9 -> conflict-free)
    #pragma unroll
    for (int r = 0; r < 8; ++r)
        sd[lane * 9 + r] = key[r].hi;
    __syncwarp();

    // edge_attr_emb: out[e, c] = d * W[c] + b[c], float4-vectorized, coalesced
    const int eg = lane >> 3;          // which of 4 edges this lane covers
    const int c4 = (lane & 7) * 4;     // 4 embedding dims
    const float4 W4 = *(const float4*)(sW + c4);
    const float4 B4 = *(const float4*)(sB + c4);
    float* eabase = o_ea + row * (long)(KSEL * DD);
    #pragma unroll 4
    for (int kk0 = 0; kk0 < KSEL; kk0 += 4) {
        int kk = kk0 + eg;             // kk <= 203 always (204 = 4*51)
        float d = sd[(kk >> 3) * 9 + (kk & 7)];
        float4 o;
        o.x = fmaf(d, W4.x, B4.x);
        o.y = fmaf(d, W4.y, B4.y);
        o.z = fmaf(d, W4.z, B4.z);
        o.w = fmaf(d, W4.w, B4.w);
        __stcs((float4*)(eabase + (long)kk * DD + c4), o);
    }
}

extern "C" void kernel_launch(void* const* d_in, const int* in_sizes, int n_in,
                              void* d_out, int out_size)
{
    const float2* locs = (const float2*)d_in[0];
    const float*  emb  = (const float*)d_in[1];
    const float*  Wv   = (const float*)d_in[2];
    const float*  bv   = (const float*)d_in[3];
    float* out = (float*)d_out;

    cudaFuncSetAttribute(edge_knn_kernel,
                         cudaFuncAttributeMaxDynamicSharedMemorySize, SMEM_BYTES);
    edge_knn_kernel<<<(BB * NN) / WARPS, THREADS, SMEM_BYTES>>>(locs, emb, Wv, bv, out);
}

// round 7
// speedup vs baseline: 1.2781x; 1.0423x over previous
#include <cuda_runtime.h>

// Problem constants (fixed by the dataset: B=32, N=1024, D=32, k = N//5 = 204)
#define BB      32
#define NN      1024
#define DD      32
#define KSEL    204
#define THREADS 256
#define WARPS   8

// Output layout (float32 concat of x, edge_index, edge_attr_emb)
#define X_ELEMS   (BB * NN * DD)            // 1,048,576
#define E_EDGES   ((long)BB * NN * KSEL)    // 6,684,672
#define EI_OFF    ((long)X_ELEMS)
#define EA_OFF    (EI_OFF + 2 * E_EDGES)    // 14,417,920

// Shared layout (bytes): slocs 8KB | per-warp scratch 8*2KB | W/b 256B
#define SMEM_BYTES (8192 + 16384 + 256)

// 64-bit key held as two float-typed registers so selects compile to FSEL
// (fma pipe) instead of SEL (alu pipe). Pure bit moves — no FP arithmetic.
struct K64 { float lo, hi; };

__device__ __forceinline__ unsigned long long k64_bits(K64 k) {
    return ((unsigned long long)__float_as_uint(k.hi) << 32) | __float_as_uint(k.lo);
}
__device__ __forceinline__ K64 k64_make(unsigned long long v) {
    K64 k;
    k.lo = __uint_as_float((unsigned)v);
    k.hi = __uint_as_float((unsigned)(v >> 32));
    return k;
}
// compare as u64 (ISETP pair, alu); select as float (FSEL, fma)
__device__ __forceinline__ bool k64_lt(K64 a, K64 b) {
    return k64_bits(a) < k64_bits(b);
}
__device__ __forceinline__ K64 k64_sel(bool take_b, K64 a, K64 b) {
    K64 r;
    r.lo = take_b ? b.lo : a.lo;
    r.hi = take_b ? b.hi : a.hi;
    return r;
}

__global__ __launch_bounds__(THREADS, 6)
void edge_knn_kernel(const float2* __restrict__ locs,
                     const float*  __restrict__ emb,
                     const float*  __restrict__ Wv,
                     const float*  __restrict__ bv,
                     float*        __restrict__ out)
{
    extern __shared__ unsigned char smem[];
    float2*             slocs   = (float2*)smem;                       // [1024]
    unsigned char*      scratch = smem + 8192;                         // 8 x 2KB
    float*              sW      = (float*)(smem + 8192 + 16384);       // [32]
    float*              sB      = sW + 32;                             // [32]

    const int tid  = threadIdx.x;
    const int lane = tid & 31;
    const int w    = tid >> 5;
    const int cta  = blockIdx.x;          // 4096 CTAs
    const int batch = cta >> 7;           // 128 CTAs per batch instance
    const int i0    = (cta & 127) << 3;   // 8 rows per CTA (one per warp)

    // ---- x copy: out[0 : 1,048,576] = init_embeddings, 64 x st.128 per CTA ----
    if (tid < 64)
        __stcs(((float4*)out) + cta * 64 + tid, ((const float4*)emb)[cta * 64 + tid]);

    // ---- stage batch locs + W/b into shared ----
    #pragma unroll
    for (int t = tid; t < NN; t += THREADS)
        slocs[t] = locs[batch * NN + t];
    if (tid < 32)      sW[tid]      = Wv[tid];
    else if (tid < 64) sB[tid - 32] = bv[tid - 32];
    __syncthreads();

    // ================= per-warp: one row i =================
    const int i = i0 + w;
    const float2 mi = slocs[i];
    unsigned long long* mycand = (unsigned long long*)(scratch + w * 2048); // [256]
    unsigned* hist = (unsigned*)mycand;   // alias: hist (1KB) inside scratch
    float*    sd   = (float*)mycand;      // alias: padded dist floats

    // zero hist
    #pragma unroll
    for (int r = 0; r < 8; ++r) hist[lane + 32 * r] = 0u;
    __syncwarp();

    // ---- pass 1: squared distances -> 256-bin histogram (uniform in sq) ----
    // Self point included (sq=0 -> bin 0); threshold rank compensates (+1).
    // sq = dx*dx + dy*dy with NO fma contraction (bit-exact vs reference).
    #pragma unroll 4
    for (int it = 0; it < NN / 32; ++it) {
        int j = it * 32 + lane;
        float2 lj = slocs[j];
        float dx = mi.x - lj.x;
        float dy = mi.y - lj.y;
        float sq = __fadd_rn(__fmul_rn(dx, dx), __fmul_rn(dy, dy));
        int bin = (int)(__fmul_rn(sq, 128.0f));   // sq in [0,2) -> [0,256)
        bin = bin > 255 ? 255 : bin;
        atomicAdd(&hist[bin], 1u);
    }
    __syncwarp();

    // ---- threshold bin: first bin with cumulative count >= KSEL+1 ----
    unsigned h[8];
    int lsum = 0;
    #pragma unroll
    for (int r = 0; r < 8; ++r) { h[r] = hist[lane * 8 + r]; lsum += (int)h[r]; }
    int incl = lsum;
    #pragma unroll
    for (int o = 1; o < 32; o <<= 1) {
        int v = __shfl_up_sync(0xFFFFFFFFu, incl, o);
        if (lane >= o) incl += v;
    }
    int c  = incl - lsum;   // exclusive prefix of this lane's 8 bins
    int tb = 256;
    #pragma unroll
    for (int r = 0; r < 8; ++r) {
        c += (int)h[r];
        if (c >= KSEL + 1 && tb == 256) tb = lane * 8 + r;
    }
    #pragma unroll
    for (int o = 16; o; o >>= 1) {
        int v = __shfl_xor_sync(0xFFFFFFFFu, tb, o);
        tb = v < tb ? v : tb;
    }
    __syncwarp();   // hist reads done; scratch may now be overwritten
    // trunc(sq*128) <= tb  <=>  sq*128 < tb+1  (exact for tb+1 <= 256)
    const float thr = (float)(tb + 1);

    // ---- pass 2: recompute sq, compact candidates (sq*128 < thr) ----
    int cnt = 0;
    #pragma unroll 4
    for (int it = 0; it < NN / 32; ++it) {
        int j = it * 32 + lane;
        float2 lj = slocs[j];
        float dx = mi.x - lj.x;
        float dy = mi.y - lj.y;
        float sq = __fadd_rn(__fmul_rn(dx, dx), __fmul_rn(dy, dy));
        bool take = (__fmul_rn(sq, 128.0f) < thr);
        unsigned m = __ballot_sync(0xFFFFFFFFu, take);
        int pos = cnt + __popc(m & ((1u << lane) - 1u));
        if (take && pos < 256)
            mycand[pos] = ((unsigned long long)__float_as_uint(sq) << 32) | (unsigned)j;
        cnt += __popc(m);
    }
    int total = cnt > 256 ? 256 : cnt;    // >= KSEL+1 by construction
    for (int p = total + lane; p < 256; p += 32)
        mycand[p] = ((unsigned long long)0x7F800000u << 32) | 0xFFFFFFFFu;  // +inf pad
    __syncwarp();

    // ---- load candidates (conflict-free), convert sq -> d on 256 survivors ----
    // Network element coordinates e = lane*8 + r (bits 0-2 = r, bits 3-7 = lane)
    // so strides 1,2,4 are register-local and only strides >=8 need SHFL.
    K64 key[8];
    #pragma unroll
    for (int r = 0; r < 8; ++r) {
        unsigned long long v = mycand[r * 32 + lane];
        float d = __fsqrt_rn(__uint_as_float((unsigned)(v >> 32)));  // sqrt(inf)=inf
        key[r] = k64_make(((unsigned long long)__float_as_uint(d) << 32) | (unsigned)v);
    }
    __syncwarp();

    // ---- bitonic sort of 256 u64 keys, e = lane*8 + r ----
    #pragma unroll
    for (int kl = 1; kl <= 8; ++kl) {
        #pragma unroll
        for (int sl = kl - 1; sl >= 0; --sl) {
            if (sl >= 3) {
                const int ls = 1 << (sl - 3);          // lane stride
                const bool lowSide = ((lane & ls) == 0);
                // kl >= 4 here, so direction is lane-based
                const bool up = (((lane >> (kl - 3)) & 1) == 0);
                const bool keepMin = (lowSide == up);
                #pragma unroll
                for (int r = 0; r < 8; ++r) {
                    K64 other;
                    other.lo = __shfl_xor_sync(0xFFFFFFFFu, key[r].lo, ls);
                    other.hi = __shfl_xor_sync(0xFFFFFFFFu, key[r].hi, ls);
                    bool less = k64_lt(key[r], other);
                    key[r] = k64_sel(less != keepMin, key[r], other);
                }
            } else {
                const int s = 1 << sl;                 // register stride
                #pragma unroll
                for (int r = 0; r < 8; ++r) {
                    if ((r & s) == 0) {
                        const int r2 = r | s;
                        bool up = (kl < 3) ? (((r >> kl) & 1) == 0)
                                           : (((lane >> (kl - 3)) & 1) == 0);
                        K64 a = key[r], b2 = key[r2];
                        bool sw = up ? k64_lt(b2, a) : k64_lt(a, b2);
                        key[r]  = k64_sel(sw, a, b2);
                        key[r2] = k64_sel(sw, b2, a);
                    }
                }
            }
        }
    }
    // element e = lane*8 + r holds rank e; rank 0 is the self point (d = 0).

    // ---- shift ranks down by one so lane covers output kk = lane*8 .. +7 ----
    {
        float t_lo = __shfl_down_sync(0xFFFFFFFFu, key[0].lo, 1);
        float t_hi = __shfl_down_sync(0xFFFFFFFFu, key[0].hi, 1);
        #pragma unroll
        for (int r = 0; r < 7; ++r) key[r] = key[r + 1];
        key[7].lo = t_lo;
        key[7].hi = t_hi;
    }

    // ---- emission ----
    const long  row  = (long)batch * NN + i;         // global node id
    float* o_src = out + EI_OFF;
    float* o_dst = o_src + E_EDGES;
    float* o_ea  = out + EA_OFF;
    const float srcv = (float)row;
    const int   jbase = batch * NN;

    // edge_index straight from registers: lane covers kk = lane*8 .. lane*8+7
    {
        float dstf[8];
        #pragma unroll
        for (int r = 0; r < 8; ++r)
            dstf[r] = (float)(jbase + (int)__float_as_uint(key[r].lo));
        float* ps = o_src + row * KSEL + lane * 8;
        float* pd = o_dst + row * KSEL + lane * 8;
        const float4 s4 = make_float4(srcv, srcv, srcv, srcv);
        if (lane < 25) {
            __stcs((float4*)ps,     s4);
            __stcs((float4*)ps + 1, s4);
            __stcs((float4*)pd,     make_float4(dstf[0], dstf[1], dstf[2], dstf[3]));
            __stcs((float4*)pd + 1, make_float4(dstf[4], dstf[5], dstf[6], dstf[7]));
        } else if (lane == 25) {   // kk 200..203 only (KSEL = 204)
            __stcs((float4*)ps, s4);
            __stcs((float4*)pd, make_float4(dstf[0], dstf[1], dstf[2], dstf[3]));
        }
    }

    // dump dist floats to padded smem (stride 9 -> conflict-free)
    #pragma unroll
    for (int r = 0; r < 8; ++r)
        sd[lane * 9 + r] = key[r].hi;
    __syncwarp();

    // edge_attr_emb: out[e, c] = d * W[c] + b[c], float4-vectorized, coalesced
    const int eg = lane >> 3;          // which of 4 edges this lane covers
    const int c4 = (lane & 7) * 4;     // 4 embedding dims
    const float4 W4 = *(const float4*)(sW + c4);
    const float4 B4 = *(const float4*)(sB + c4);
    float* eabase = o_ea + row * (long)(KSEL * DD);
    #pragma unroll 4
    for (int kk0 = 0; kk0 < KSEL; kk0 += 4) {
        int kk = kk0 + eg;             // kk <= 203 always (204 = 4*51)
        float d = sd[(kk >> 3) * 9 + (kk & 7)];
        float4 o;
        o.x = fmaf(d, W4.x, B4.x);
        o.y = fmaf(d, W4.y, B4.y);
        o.z = fmaf(d, W4.z, B4.z);
        o.w = fmaf(d, W4.w, B4.w);
        __stcs((float4*)(eabase + (long)kk * DD + c4), o);
    }
}

extern "C" void kernel_launch(void* const* d_in, const int* in_sizes, int n_in,
                              void* d_out, int out_size)
{
    const float2* locs = (const float2*)d_in[0];
    const float*  emb  = (const float*)d_in[1];
    const float*  Wv   = (const float*)d_in[2];
    const float*  bv   = (const float*)d_in[3];
    float* out = (float*)d_out;

    cudaFuncSetAttribute(edge_knn_kernel,
                         cudaFuncAttributeMaxDynamicSharedMemorySize, SMEM_BYTES);
    edge_knn_kernel<<<(BB * NN) / WARPS, THREADS, SMEM_BYTES>>>(locs, emb, Wv, bv, out);
}

// round 8
// speedup vs baseline: 1.3142x; 1.0282x over previous
#include <cuda_runtime.h>

// Problem constants (fixed by the dataset: B=32, N=1024, D=32, k = N//5 = 204)
#define BB      32
#define NN      1024
#define DD      32
#define KSEL    204
#define THREADS 256
#define WARPS   8

// Output layout (float32 concat of x, edge_index, edge_attr_emb)
#define X_ELEMS   (BB * NN * DD)            // 1,048,576
#define E_EDGES   ((long)BB * NN * KSEL)    // 6,684,672
#define EI_OFF    ((long)X_ELEMS)
#define EA_OFF    (EI_OFF + 2 * E_EDGES)    // 14,417,920

// Shared layout (bytes): slocs 8KB | per-warp scratch 8*2KB | W/b 256B
#define SMEM_BYTES (8192 + 16384 + 256)

// 64-bit key held as two float-typed registers so selects compile to FSEL
// (fma pipe) instead of SEL (alu pipe). Pure bit moves — no FP arithmetic.
struct K64 { float lo, hi; };

__device__ __forceinline__ unsigned long long k64_bits(K64 k) {
    return ((unsigned long long)__float_as_uint(k.hi) << 32) | __float_as_uint(k.lo);
}
__device__ __forceinline__ K64 k64_make(unsigned long long v) {
    K64 k;
    k.lo = __uint_as_float((unsigned)v);
    k.hi = __uint_as_float((unsigned)(v >> 32));
    return k;
}
// compare as u64 (ISETP pair, alu); select as float (FSEL, fma)
__device__ __forceinline__ bool k64_lt(K64 a, K64 b) {
    return k64_bits(a) < k64_bits(b);
}
__device__ __forceinline__ K64 k64_sel(bool take_b, K64 a, K64 b) {
    K64 r;
    r.lo = take_b ? b.lo : a.lo;
    r.hi = take_b ? b.hi : a.hi;
    return r;
}

__global__ __launch_bounds__(THREADS, 7)
void edge_knn_kernel(const float2* __restrict__ locs,
                     const float*  __restrict__ emb,
                     const float*  __restrict__ Wv,
                     const float*  __restrict__ bv,
                     float*        __restrict__ out)
{
    extern __shared__ unsigned char smem[];
    float2*             slocs   = (float2*)smem;                       // [1024]
    unsigned char*      scratch = smem + 8192;                         // 8 x 2KB
    float*              sW      = (float*)(smem + 8192 + 16384);       // [32]
    float*              sB      = sW + 32;                             // [32]

    const int tid  = threadIdx.x;
    const int lane = tid & 31;
    const int w    = tid >> 5;
    const int cta  = blockIdx.x;          // 4096 CTAs
    const int batch = cta >> 7;           // 128 CTAs per batch instance
    const int i0    = (cta & 127) << 3;   // 8 rows per CTA (one per warp)

    // ---- x copy: out[0 : 1,048,576] = init_embeddings, 64 x st.128 per CTA ----
    if (tid < 64)
        __stcs(((float4*)out) + cta * 64 + tid, ((const float4*)emb)[cta * 64 + tid]);

    // ---- stage batch locs + W/b into shared ----
    #pragma unroll
    for (int t = tid; t < NN; t += THREADS)
        slocs[t] = locs[batch * NN + t];
    if (tid < 32)      sW[tid]      = Wv[tid];
    else if (tid < 64) sB[tid - 32] = bv[tid - 32];
    __syncthreads();

    // ================= per-warp: one row i =================
    const int i = i0 + w;
    const float2 mi = slocs[i];
    unsigned long long* mycand = (unsigned long long*)(scratch + w * 2048); // [256]
    unsigned* hist = (unsigned*)mycand;   // alias: hist (1KB) inside scratch
    float*    sd   = (float*)mycand;      // alias: padded dist floats

    // zero hist (u64 stores: 4 per lane)
    #pragma unroll
    for (int r = 0; r < 4; ++r) mycand[lane + 32 * r] = 0ULL;
    __syncwarp();

    // ---- pass 1: squared distances -> 256-bin histogram (uniform in sq) ----
    // Self point included (sq=0 -> bin 0); threshold rank compensates (+1).
    // sq = dx*dx + dy*dy with NO fma contraction (bit-exact vs reference).
    #pragma unroll 4
    for (int it = 0; it < NN / 32; ++it) {
        int j = it * 32 + lane;
        float2 lj = slocs[j];
        float dx = mi.x - lj.x;
        float dy = mi.y - lj.y;
        float sq = __fadd_rn(__fmul_rn(dx, dx), __fmul_rn(dy, dy));
        int bin = (int)(__fmul_rn(sq, 128.0f));   // sq in [0,2) -> [0,256)
        bin = bin > 255 ? 255 : bin;
        atomicAdd(&hist[bin], 1u);
    }
    __syncwarp();

    // ---- threshold bin: first bin with cumulative count >= KSEL+1 ----
    unsigned h[8];
    int lsum = 0;
    #pragma unroll
    for (int r = 0; r < 8; ++r) { h[r] = hist[lane * 8 + r]; lsum += (int)h[r]; }
    int incl = lsum;
    #pragma unroll
    for (int o = 1; o < 32; o <<= 1) {
        int v = __shfl_up_sync(0xFFFFFFFFu, incl, o);
        if (lane >= o) incl += v;
    }
    int c  = incl - lsum;   // exclusive prefix of this lane's 8 bins
    int tb = 256;
    #pragma unroll
    for (int r = 0; r < 8; ++r) {
        c += (int)h[r];
        if (c >= KSEL + 1 && tb == 256) tb = lane * 8 + r;
    }
    #pragma unroll
    for (int o = 16; o; o >>= 1) {
        int v = __shfl_xor_sync(0xFFFFFFFFu, tb, o);
        tb = v < tb ? v : tb;
    }
    __syncwarp();   // hist reads done; scratch may now be overwritten
    // trunc(sq*128) <= tb  <=>  sq*128 < tb+1  (exact for tb+1 <= 256)
    const float thr = (float)(tb + 1);

    // ---- pass 2: recompute sq, compact candidates (sq*128 < thr) ----
    int cnt = 0;
    #pragma unroll 4
    for (int it = 0; it < NN / 32; ++it) {
        int j = it * 32 + lane;
        float2 lj = slocs[j];
        float dx = mi.x - lj.x;
        float dy = mi.y - lj.y;
        float sq = __fadd_rn(__fmul_rn(dx, dx), __fmul_rn(dy, dy));
        bool take = (__fmul_rn(sq, 128.0f) < thr);
        unsigned m = __ballot_sync(0xFFFFFFFFu, take);
        int pos = cnt + __popc(m & ((1u << lane) - 1u));
        if (take && pos < 256)
            mycand[pos] = ((unsigned long long)__float_as_uint(sq) << 32) | (unsigned)j;
        cnt += __popc(m);
    }
    int total = cnt > 256 ? 256 : cnt;    // >= KSEL+1 by construction
    for (int p = total + lane; p < 256; p += 32)
        mycand[p] = ((unsigned long long)0x7F800000u << 32) | 0xFFFFFFFFu;  // +inf pad
    __syncwarp();

    // ---- load candidates (conflict-free), convert sq -> d on 256 survivors ----
    // Network element coordinates e = lane*8 + r (bits 0-2 = r, bits 3-7 = lane)
    // so strides 1,2,4 are register-local and only strides >=8 need SHFL.
    K64 key[8];
    #pragma unroll
    for (int r = 0; r < 8; ++r) {
        unsigned long long v = mycand[r * 32 + lane];
        float d = __fsqrt_rn(__uint_as_float((unsigned)(v >> 32)));  // sqrt(inf)=inf
        key[r] = k64_make(((unsigned long long)__float_as_uint(d) << 32) | (unsigned)v);
    }
    __syncwarp();

    // ---- bitonic sort of 256 u64 keys, e = lane*8 + r ----
    #pragma unroll
    for (int kl = 1; kl <= 8; ++kl) {
        #pragma unroll
        for (int sl = kl - 1; sl >= 0; --sl) {
            if (sl >= 3) {
                const int ls = 1 << (sl - 3);          // lane stride
                const bool lowSide = ((lane & ls) == 0);
                // kl >= 4 here, so direction is lane-based
                const bool up = (((lane >> (kl - 3)) & 1) == 0);
                const bool keepMin = (lowSide == up);
                #pragma unroll
                for (int r = 0; r < 8; ++r) {
                    K64 other;
                    other.lo = __shfl_xor_sync(0xFFFFFFFFu, key[r].lo, ls);
                    other.hi = __shfl_xor_sync(0xFFFFFFFFu, key[r].hi, ls);
                    bool less = k64_lt(key[r], other);
                    key[r] = k64_sel(less != keepMin, key[r], other);
                }
            } else {
                const int s = 1 << sl;                 // register stride
                #pragma unroll
                for (int r = 0; r < 8; ++r) {
                    if ((r & s) == 0) {
                        const int r2 = r | s;
                        bool up = (kl < 3) ? (((r >> kl) & 1) == 0)
                                           : (((lane >> (kl - 3)) & 1) == 0);
                        K64 a = key[r], b2 = key[r2];
                        bool sw = up ? k64_lt(b2, a) : k64_lt(a, b2);
                        key[r]  = k64_sel(sw, a, b2);
                        key[r2] = k64_sel(sw, b2, a);
                    }
                }
            }
        }
    }
    // element e = lane*8 + r holds rank e; rank 0 is the self point (d = 0).

    // ---- shift ranks down by one so lane covers output kk = lane*8 .. +7 ----
    {
        float t_lo = __shfl_down_sync(0xFFFFFFFFu, key[0].lo, 1);
        float t_hi = __shfl_down_sync(0xFFFFFFFFu, key[0].hi, 1);
        #pragma unroll
        for (int r = 0; r < 7; ++r) key[r] = key[r + 1];
        key[7].lo = t_lo;
        key[7].hi = t_hi;
    }

    // ---- emission ----
    const long  row  = (long)batch * NN + i;         // global node id
    float* o_src = out + EI_OFF;
    float* o_dst = o_src + E_EDGES;
    float* o_ea  = out + EA_OFF;
    const float srcv = (float)row;
    const int   jbase = batch * NN;

    // edge_index straight from registers: lane covers kk = lane*8 .. lane*8+7
    {
        float dstf[8];
        #pragma unroll
        for (int r = 0; r < 8; ++r)
            dstf[r] = (float)(jbase + (int)__float_as_uint(key[r].lo));
        float* ps = o_src + row * KSEL + lane * 8;
        float* pd = o_dst + row * KSEL + lane * 8;
        const float4 s4 = make_float4(srcv, srcv, srcv, srcv);
        if (lane < 25) {
            __stcs((float4*)ps,     s4);
            __stcs((float4*)ps + 1, s4);
            __stcs((float4*)pd,     make_float4(dstf[0], dstf[1], dstf[2], dstf[3]));
            __stcs((float4*)pd + 1, make_float4(dstf[4], dstf[5], dstf[6], dstf[7]));
        } else if (lane == 25) {   // kk 200..203 only (KSEL = 204)
            __stcs((float4*)ps, s4);
            __stcs((float4*)pd, make_float4(dstf[0], dstf[1], dstf[2], dstf[3]));
        }
    }

    // dump dist floats to padded smem (stride 9 -> conflict-free)
    #pragma unroll
    for (int r = 0; r < 8; ++r)
        sd[lane * 9 + r] = key[r].hi;
    __syncwarp();

    // edge_attr_emb: out[e, c] = d * W[c] + b[c], float4-vectorized, coalesced
    const int eg = lane >> 3;          // which of 4 edges this lane covers
    const int c4 = (lane & 7) * 4;     // 4 embedding dims
    const float4 W4 = *(const float4*)(sW + c4);
    const float4 B4 = *(const float4*)(sB + c4);
    float* eabase = o_ea + row * (long)(KSEL * DD);
    #pragma unroll 4
    for (int kk0 = 0; kk0 < KSEL; kk0 += 4) {
        int kk = kk0 + eg;             // kk <= 203 always (204 = 4*51)
        float d = sd[(kk >> 3) * 9 + (kk & 7)];
        float4 o;
        o.x = fmaf(d, W4.x, B4.x);
        o.y = fmaf(d, W4.y, B4.y);
        o.z = fmaf(d, W4.z, B4.z);
        o.w = fmaf(d, W4.w, B4.w);
        __stcs((float4*)(eabase + (long)kk * DD + c4), o);
    }
}

extern "C" void kernel_launch(void* const* d_in, const int* in_sizes, int n_in,
                              void* d_out, int out_size)
{
    const float2* locs = (const float2*)d_in[0];
    const float*  emb  = (const float*)d_in[1];
    const float*  Wv   = (const float*)d_in[2];
    const float*  bv   = (const float*)d_in[3];
    float* out = (float*)d_out;

    cudaFuncSetAttribute(edge_knn_kernel,
                         cudaFuncAttributeMaxDynamicSharedMemorySize, SMEM_BYTES);
    edge_knn_kernel<<<(BB * NN) / WARPS, THREADS, SMEM_BYTES>>>(locs, emb, Wv, bv, out);
}